// round 1
// baseline (speedup 1.0000x reference)
#include <cuda_runtime.h>
#include <math.h>

// ---------------------------------------------------------------------------
// VQ-VAE forward, fp32 direct-conv implementation.
// Shapes:
//   x        [32,3,128,128]
//   e1 out   [32,64,64,64]    (k4 s2 p1, relu)
//   e2 out   [32,128,32,32]   (k4 s2 p1, relu)
//   e3 out   [32,128,32,32]   (k3 s1 p1)
//   res x2   (3x3 H->32 relu-in, 1x1 32->H relu-in + residual add)
//   pre out  [32,64,32,32]    (1x1, relu-in fused from final stack relu)
//   VQ       N=32768 positions, K=512 codes, D=64
//   d1 out   [32,128,32,32]   (k3 s1 p1)
//   res x2
//   dt1 out  [32,64,64,64]    (deconv k4 s2 p1, relu-in fused, relu-out)
//   dt2 out  [32,3,128,128]   (deconv k4 s2 p1)
// Output layout: [loss, x_recon(1572864), perplexity]
// ---------------------------------------------------------------------------

// Scratch (device globals; no allocation allowed)
__device__ float g_A[32u * 64 * 64 * 64];    // e1 out / dt1 out (reused)
__device__ float g_B[32u * 128 * 32 * 32];   // e2 out
__device__ float g_C[32u * 128 * 32 * 32];   // e3 out + encoder res stack (in-place)
__device__ float g_T[32u * 32 * 32 * 32];    // res 3x3 intermediate
__device__ float g_Z[32u * 64 * 32 * 32];    // pre-VQ z
__device__ float g_Q[32u * 64 * 32 * 32];    // quantized q
__device__ float g_G[32u * 128 * 32 * 32];   // decoder d1 out + res stack (in-place)
__device__ int   g_idx[32768];
__device__ int   g_hist[512];
__device__ float g_cnorm[512];
__device__ float g_partial[2048];

// ---------------------------------------------------------------------------
// Generic direct conv: per-thread tile = TX(=4) outputs along x, TCO output
// channels. Weight loads are uniform per block (broadcast); input window loads
// are coalesced along x.
// ---------------------------------------------------------------------------
template <int KH, int KW, int S, int P, int TCO,
          bool IN_RELU, bool OUT_RELU, bool BIAS, bool ADD>
__global__ __launch_bounds__(128)
void conv2d_k(const float* __restrict__ in, const float* __restrict__ wt,
              const float* __restrict__ bs, float* __restrict__ out,
              const float* __restrict__ res,
              int Cin, int Hin, int Win, int Cout, int Hout, int Wout)
{
    constexpr int TX = 4;
    constexpr int WINW = (TX - 1) * S + KW;

    int tid = blockIdx.x * blockDim.x + threadIdx.x;
    int ntiles = (Hout * Wout) / TX;
    if (tid >= ntiles) return;
    int s0  = tid * TX;
    int ox0 = s0 % Wout;
    int oy  = s0 / Wout;
    int co0 = blockIdx.y * TCO;
    int b   = blockIdx.z;

    float acc[TCO][TX];
#pragma unroll
    for (int c = 0; c < TCO; c++) {
        float bv = BIAS ? bs[co0 + c] : 0.f;
#pragma unroll
        for (int j = 0; j < TX; j++) acc[c][j] = bv;
    }

    const float* inb = in + (size_t)b * Cin * Hin * Win;
    const int ixb = ox0 * S - P;

    for (int ci = 0; ci < Cin; ci++) {
        const float* ip = inb + (size_t)ci * Hin * Win;
#pragma unroll
        for (int ky = 0; ky < KH; ky++) {
            int iy = oy * S - P + ky;
            if (iy < 0 || iy >= Hin) continue;
            const float* row = ip + (size_t)iy * Win;
            float win[WINW];
#pragma unroll
            for (int m = 0; m < WINW; m++) {
                int ix = ixb + m;
                float v = (ix >= 0 && ix < Win) ? row[ix] : 0.f;
                if (IN_RELU) v = fmaxf(v, 0.f);
                win[m] = v;
            }
#pragma unroll
            for (int c = 0; c < TCO; c++) {
                const float* wp = wt + (((size_t)(co0 + c) * Cin + ci) * KH + ky) * KW;
#pragma unroll
                for (int kx = 0; kx < KW; kx++) {
                    float wv = wp[kx];
#pragma unroll
                    for (int j = 0; j < TX; j++)
                        acc[c][j] = fmaf(win[j * S + kx], wv, acc[c][j]);
                }
            }
        }
    }

#pragma unroll
    for (int c = 0; c < TCO; c++) {
        size_t o = (((size_t)b * Cout + (co0 + c)) * Hout + oy) * Wout + ox0;
#pragma unroll
        for (int j = 0; j < TX; j++) {
            float v = acc[c][j];
            if (ADD) v += res[o + j];
            if (OUT_RELU) v = fmaxf(v, 0.f);
            out[o + j] = v;
        }
    }
}

// ---------------------------------------------------------------------------
// ConvTranspose2d(k=4, s=2, p=1) as a direct gather.
// For output (oy,ox): 2 valid ky taps (parity of oy) and 2 valid kx taps
// (parity of ox). iy = (oy - 2 + ky) >> 1, ky = (oy&1) + 2t.
// Weight layout OIHW: w[Cout, Cin, 4, 4] (no flip; correlation).
// ---------------------------------------------------------------------------
template <int TCO, bool IN_RELU, bool OUT_RELU>
__global__ __launch_bounds__(128)
void deconv4s2p1_k(const float* __restrict__ in, const float* __restrict__ wt,
                   const float* __restrict__ bs, float* __restrict__ out,
                   int Cin, int Hin, int Win, int Cout, int Hout, int Wout)
{
    constexpr int TX = 4;
    int tid = blockIdx.x * blockDim.x + threadIdx.x;
    int ntiles = (Hout * Wout) / TX;
    if (tid >= ntiles) return;
    int s0  = tid * TX;
    int ox0 = s0 % Wout;   // multiple of 4 -> even
    int oy  = s0 / Wout;
    int co0 = blockIdx.y * TCO;
    int b   = blockIdx.z;

    float acc[TCO][TX];
#pragma unroll
    for (int c = 0; c < TCO; c++) {
        float bv = bs[co0 + c];
#pragma unroll
        for (int j = 0; j < TX; j++) acc[c][j] = bv;
    }

    const int ixb = ox0 / 2 - 1;      // input window base: u[m] = in[iy, ixb+m], m=0..3
    const int oyp = oy & 1;
    const float* inb = in + (size_t)b * Cin * Hin * Win;

    for (int ci = 0; ci < Cin; ci++) {
        const float* ip = inb + (size_t)ci * Hin * Win;
#pragma unroll
        for (int t = 0; t < 2; t++) {
            int ky = oyp + 2 * t;
            int iy = (oy - 2 + ky) >> 1;
            if (iy < 0 || iy >= Hin) continue;
            const float* row = ip + (size_t)iy * Win;
            float u[4];
#pragma unroll
            for (int m = 0; m < 4; m++) {
                int ix = ixb + m;
                float v = (ix >= 0 && ix < Win) ? row[ix] : 0.f;
                if (IN_RELU) v = fmaxf(v, 0.f);
                u[m] = v;
            }
#pragma unroll
            for (int c = 0; c < TCO; c++) {
                const float* wp = wt + (((size_t)(co0 + c) * Cin + ci) * 4 + ky) * 4;
#pragma unroll
                for (int j = 0; j < TX; j++) {
                    int jo = j & 1;           // kx parity
                    int sh = (j + 1) >> 1;    // window shift
                    acc[c][j] = fmaf(u[sh],     wp[jo],     acc[c][j]);   // tx=0: kx=jo
                    acc[c][j] = fmaf(u[sh + 1], wp[2 + jo], acc[c][j]);   // tx=1: kx=2+jo
                }
            }
        }
    }

#pragma unroll
    for (int c = 0; c < TCO; c++) {
        size_t o = (((size_t)b * Cout + (co0 + c)) * Hout + oy) * Wout + ox0;
#pragma unroll
        for (int j = 0; j < TX; j++) {
            float v = acc[c][j];
            if (OUT_RELU) v = fmaxf(v, 0.f);
            out[o + j] = v;
        }
    }
}

// ---------------------------------------------------------------------------
// VQ: codebook norms, argmin + gather, histogram, MSE, scalars.
// ---------------------------------------------------------------------------
__global__ void cnorm_kernel(const float* __restrict__ cb, float* __restrict__ cn)
{
    int k = blockIdx.x * blockDim.x + threadIdx.x;
    if (k >= 512) return;
    const float* c = cb + k * 64;
    float s = 0.f;
#pragma unroll
    for (int d = 0; d < 64; d++) s = fmaf(c[d], c[d], s);
    cn[k] = s;
}

__global__ __launch_bounds__(256)
void vq_kernel(const float* __restrict__ z, const float* __restrict__ cb,
               const float* __restrict__ cn, int* __restrict__ idx,
               float* __restrict__ q)
{
    int p = blockIdx.x * blockDim.x + threadIdx.x;  // position 0..32767
    if (p >= 32768) return;
    int b = p >> 10, s = p & 1023;
    const float* zp = z + (size_t)b * 64 * 1024 + s;
    float zv[64];
#pragma unroll
    for (int d = 0; d < 64; d++) zv[d] = zp[d * 1024];

    float best = 3.4e38f;
    int bk = 0;
    for (int k = 0; k < 512; k++) {
        const float* c = cb + k * 64;
        float d0 = 0.f, d1 = 0.f, d2 = 0.f, d3 = 0.f;
#pragma unroll
        for (int d = 0; d < 64; d += 4) {
            d0 = fmaf(zv[d],     c[d],     d0);
            d1 = fmaf(zv[d + 1], c[d + 1], d1);
            d2 = fmaf(zv[d + 2], c[d + 2], d2);
            d3 = fmaf(zv[d + 3], c[d + 3], d3);
        }
        float dist = cn[k] - 2.f * ((d0 + d1) + (d2 + d3));
        if (dist < best) { best = dist; bk = k; }   // strict <: first-min like jnp.argmin
    }
    idx[p] = bk;
    float* qp = q + (size_t)b * 64 * 1024 + s;
    const float* c = cb + bk * 64;
#pragma unroll
    for (int d = 0; d < 64; d++) qp[d * 1024] = c[d];
}

__global__ void hist_zero_kernel(int* __restrict__ hist)
{
    int k = blockIdx.x * blockDim.x + threadIdx.x;
    if (k < 512) hist[k] = 0;
}

__global__ void hist_kernel(const int* __restrict__ idx, int* __restrict__ hist)
{
    int p = blockIdx.x * blockDim.x + threadIdx.x;
    if (p < 32768) atomicAdd(&hist[idx[p]], 1);   // integer atomics: deterministic
}

__global__ __launch_bounds__(256)
void mse_partial_kernel(const float* __restrict__ q, const float* __restrict__ z,
                        float* __restrict__ partial)
{
    __shared__ float sm[256];
    int base = blockIdx.x * 1024;
    float s = 0.f;
    for (int i = threadIdx.x; i < 1024; i += 256) {
        float d = q[base + i] - z[base + i];
        s = fmaf(d, d, s);
    }
    sm[threadIdx.x] = s;
    __syncthreads();
    for (int off = 128; off > 0; off >>= 1) {
        if (threadIdx.x < off) sm[threadIdx.x] += sm[threadIdx.x + off];
        __syncthreads();
    }
    if (threadIdx.x == 0) partial[blockIdx.x] = sm[0];
}

__global__ __launch_bounds__(256)
void loss_kernel(const float* __restrict__ partial, float* __restrict__ out0)
{
    __shared__ float sm[256];
    float s = 0.f;
    for (int i = threadIdx.x; i < 2048; i += 256) s += partial[i];
    sm[threadIdx.x] = s;
    __syncthreads();
    for (int off = 128; off > 0; off >>= 1) {
        if (threadIdx.x < off) sm[threadIdx.x] += sm[threadIdx.x + off];
        __syncthreads();
    }
    // loss = q_latent + beta * e_latent = (1 + 0.25) * mse
    if (threadIdx.x == 0) out0[0] = 1.25f * sm[0] / 2097152.0f;
}

__global__ __launch_bounds__(512)
void perp_kernel(const int* __restrict__ hist, float* __restrict__ outp)
{
    __shared__ float sm[512];
    int k = threadIdx.x;
    float p = (float)hist[k] * (1.0f / 32768.0f);
    sm[k] = p * logf(p + 1e-10f);
    __syncthreads();
    for (int off = 256; off > 0; off >>= 1) {
        if (k < off) sm[k] += sm[k + off];
        __syncthreads();
    }
    if (k == 0) outp[0] = expf(-sm[0]);
}

// ---------------------------------------------------------------------------
// Launch
// ---------------------------------------------------------------------------
extern "C" void kernel_launch(void* const* d_in, const int* in_sizes, int n_in,
                              void* d_out, int out_size)
{
    const float* x     = (const float*)d_in[0];
    const float* e_w1  = (const float*)d_in[1];
    const float* e_b1  = (const float*)d_in[2];
    const float* e_w2  = (const float*)d_in[3];
    const float* e_b2  = (const float*)d_in[4];
    const float* e_w3  = (const float*)d_in[5];
    const float* e_b3  = (const float*)d_in[6];
    const float* e_r1a = (const float*)d_in[7];
    const float* e_r1b = (const float*)d_in[8];
    const float* e_r2a = (const float*)d_in[9];
    const float* e_r2b = (const float*)d_in[10];
    const float* pre_w = (const float*)d_in[11];
    const float* pre_b = (const float*)d_in[12];
    const float* cb    = (const float*)d_in[13];
    const float* d_w1  = (const float*)d_in[14];
    const float* d_b1  = (const float*)d_in[15];
    const float* d_r1a = (const float*)d_in[16];
    const float* d_r1b = (const float*)d_in[17];
    const float* d_r2a = (const float*)d_in[18];
    const float* d_r2b = (const float*)d_in[19];
    const float* dt_w1 = (const float*)d_in[20];
    const float* dt_b1 = (const float*)d_in[21];
    const float* dt_w2 = (const float*)d_in[22];
    const float* dt_b2 = (const float*)d_in[23];
    float* out = (float*)d_out;

    float *A, *Bf, *Cc, *T, *Z, *Q, *G, *cn, *part;
    int *idx, *hist;
    cudaGetSymbolAddress((void**)&A,   g_A);
    cudaGetSymbolAddress((void**)&Bf,  g_B);
    cudaGetSymbolAddress((void**)&Cc,  g_C);
    cudaGetSymbolAddress((void**)&T,   g_T);
    cudaGetSymbolAddress((void**)&Z,   g_Z);
    cudaGetSymbolAddress((void**)&Q,   g_Q);
    cudaGetSymbolAddress((void**)&G,   g_G);
    cudaGetSymbolAddress((void**)&cn,  g_cnorm);
    cudaGetSymbolAddress((void**)&part, g_partial);
    cudaGetSymbolAddress((void**)&idx,  g_idx);
    cudaGetSymbolAddress((void**)&hist, g_hist);

    const int NB = 32;
    dim3 blk(128);

    // ---- encoder ----
    // e1: [32,3,128,128] -> [32,64,64,64], k4 s2 p1, relu
    {
        dim3 grid((64 * 64 / 4 + 127) / 128, 64 / 2, NB);
        conv2d_k<4, 4, 2, 1, 2, false, true, true, false><<<grid, blk>>>(
            x, e_w1, e_b1, A, nullptr, 3, 128, 128, 64, 64, 64);
    }
    // e2: -> [32,128,32,32], k4 s2 p1, relu
    {
        dim3 grid((32 * 32 / 4 + 127) / 128, 128 / 2, NB);
        conv2d_k<4, 4, 2, 1, 2, false, true, true, false><<<grid, blk>>>(
            A, e_w2, e_b2, Bf, nullptr, 64, 64, 64, 128, 32, 32);
    }
    // e3: -> [32,128,32,32], k3 s1 p1
    {
        dim3 grid((32 * 32 / 4 + 127) / 128, 128 / 2, NB);
        conv2d_k<3, 3, 1, 1, 2, false, false, true, false><<<grid, blk>>>(
            Bf, e_w3, e_b3, Cc, nullptr, 128, 32, 32, 128, 32, 32);
    }
    // encoder res stack (2 blocks), in-place on Cc
    for (int rb = 0; rb < 2; rb++) {
        const float* wa = (rb == 0) ? e_r1a : e_r2a;
        const float* wb = (rb == 0) ? e_r1b : e_r2b;
        dim3 grid3((32 * 32 / 4 + 127) / 128, 32 / 2, NB);
        conv2d_k<3, 3, 1, 1, 2, true, false, false, false><<<grid3, blk>>>(
            Cc, wa, nullptr, T, nullptr, 128, 32, 32, 32, 32, 32);
        dim3 grid1((32 * 32 / 4 + 127) / 128, 128 / 2, NB);
        conv2d_k<1, 1, 1, 0, 2, true, false, false, true><<<grid1, blk>>>(
            T, wb, nullptr, Cc, Cc, 32, 32, 32, 128, 32, 32);
    }
    // pre-VQ 1x1 (fused final-stack ReLU on input): Cc -> Z [32,64,32,32]
    {
        dim3 grid((32 * 32 / 4 + 127) / 128, 64 / 2, NB);
        conv2d_k<1, 1, 1, 0, 2, true, false, true, false><<<grid, blk>>>(
            Cc, pre_w, pre_b, Z, nullptr, 128, 32, 32, 64, 32, 32);
    }

    // ---- vector quantizer ----
    cnorm_kernel<<<2, 256>>>(cb, cn);
    vq_kernel<<<128, 256>>>(Z, cb, cn, idx, Q);
    hist_zero_kernel<<<2, 256>>>(hist);
    hist_kernel<<<128, 256>>>(idx, hist);
    mse_partial_kernel<<<2048, 256>>>(Q, Z, part);
    loss_kernel<<<1, 256>>>(part, out);            // out[0] = loss
    perp_kernel<<<1, 512>>>(hist, out + (out_size - 1));  // last = perplexity

    // ---- decoder ----
    // d1: Q -> G [32,128,32,32], k3 s1 p1
    {
        dim3 grid((32 * 32 / 4 + 127) / 128, 128 / 2, NB);
        conv2d_k<3, 3, 1, 1, 2, false, false, true, false><<<grid, blk>>>(
            Q, d_w1, d_b1, G, nullptr, 64, 32, 32, 128, 32, 32);
    }
    // decoder res stack, in-place on G
    for (int rb = 0; rb < 2; rb++) {
        const float* wa = (rb == 0) ? d_r1a : d_r2a;
        const float* wb = (rb == 0) ? d_r1b : d_r2b;
        dim3 grid3((32 * 32 / 4 + 127) / 128, 32 / 2, NB);
        conv2d_k<3, 3, 1, 1, 2, true, false, false, false><<<grid3, blk>>>(
            G, wa, nullptr, T, nullptr, 128, 32, 32, 32, 32, 32);
        dim3 grid1((32 * 32 / 4 + 127) / 128, 128 / 2, NB);
        conv2d_k<1, 1, 1, 0, 2, true, false, false, true><<<grid1, blk>>>(
            T, wb, nullptr, G, G, 32, 32, 32, 128, 32, 32);
    }
    // dt1: G -> A [32,64,64,64], deconv k4 s2 p1, relu-in (fused stack ReLU), relu-out
    {
        dim3 grid((64 * 64 / 4 + 127) / 128, 64 / 2, NB);
        deconv4s2p1_k<2, true, true><<<grid, blk>>>(
            G, dt_w1, dt_b1, A, 128, 32, 32, 64, 64, 64);
    }
    // dt2: A -> x_recon [32,3,128,128] directly into d_out+1
    {
        dim3 grid((128 * 128 / 4 + 127) / 128, 3, NB);
        deconv4s2p1_k<1, false, false><<<grid, blk>>>(
            A, dt_w2, dt_b2, out + 1, 64, 64, 64, 3, 128, 128);
    }
}

// round 2
// speedup vs baseline: 1.8861x; 1.8861x over previous
#include <cuda_runtime.h>
#include <math.h>

// ---------------------------------------------------------------------------
// VQ-VAE forward, fp32 direct conv. Round 2: TX=8 register tiles, float4
// loads, all shapes as template constants, fused VQ error.
// Output layout: [loss, x_recon(1572864), perplexity]
// ---------------------------------------------------------------------------

// Scratch (device globals; no allocation allowed)
__device__ float g_A[32u * 64 * 64 * 64];    // e1 out / dt1 out (reused)
__device__ float g_B[32u * 128 * 32 * 32];   // e2 out
__device__ float g_C[32u * 128 * 32 * 32];   // e3 out + encoder res stack (in-place)
__device__ float g_T[32u * 32 * 32 * 32];    // res 3x3 intermediate
__device__ float g_Z[32u * 64 * 32 * 32];    // pre-VQ z
__device__ float g_Q[32u * 64 * 32 * 32];    // quantized q
__device__ float g_G[32u * 128 * 32 * 32];   // decoder d1 out + res stack (in-place)
__device__ int   g_idx[32768];
__device__ int   g_hist[512];
__device__ float g_cnorm[512];
__device__ float g_err[32768];

// ---------------------------------------------------------------------------
// Direct conv, fully templated. Per-thread tile: TX=8 outputs along x,
// TCO output channels. float4 window loads; float4 weight loads when KW==4.
// ---------------------------------------------------------------------------
template <int KH, int KW, int S, int P, int TCO,
          int CIN, int HIN, int WIN, int COUT, int HOUT, int WOUT,
          bool IN_RELU, bool OUT_RELU, bool BIAS, bool ADD>
__global__ __launch_bounds__(128)
void conv_k(const float* __restrict__ in, const float* __restrict__ wt,
            const float* __restrict__ bs, float* __restrict__ out,
            const float* __restrict__ res)
{
    constexpr int TX   = 8;
    constexpr int WINW = (TX - 1) * S + KW;
    constexpr int TILES = HOUT * WOUT / TX;
    static_assert(TILES % 128 == 0, "tile count must fill blocks");
    static_assert(P == 0 || (WINW - 2) % 4 == 0, "window vectorization");

    int tid = blockIdx.x * 128 + threadIdx.x;
    int ox0 = (tid * TX) % WOUT;
    int oy  = (tid * TX) / WOUT;
    int co0 = blockIdx.y * TCO;
    int b   = blockIdx.z;

    float acc[TCO][TX];
#pragma unroll
    for (int c = 0; c < TCO; c++) {
        float bv = BIAS ? __ldg(bs + co0 + c) : 0.f;
#pragma unroll
        for (int j = 0; j < TX; j++) acc[c][j] = bv;
    }

    const float* inb = in + (size_t)b * CIN * HIN * WIN;
    const int ixb = ox0 * S - P;

#pragma unroll 1
    for (int ci = 0; ci < CIN; ci++) {
        const float* ip  = inb + ci * HIN * WIN;
        const float* wci = wt + ((size_t)co0 * CIN + ci) * KH * KW;
#pragma unroll
        for (int ky = 0; ky < KH; ky++) {
            int iy = oy * S - P + ky;
            if (P > 0 && (iy < 0 || iy >= HIN)) continue;
            const float* row = ip + iy * WIN;
            float w[WINW];
            if constexpr (P == 0) {
                float4 v0 = *(const float4*)(row + ox0);
                float4 v1 = *(const float4*)(row + ox0 + 4);
                w[0] = v0.x; w[1] = v0.y; w[2] = v0.z; w[3] = v0.w;
                w[4] = v1.x; w[5] = v1.y; w[6] = v1.z; w[7] = v1.w;
            } else {
                w[0] = (ixb >= 0) ? row[ixb] : 0.f;
#pragma unroll
                for (int m = 0; m < (WINW - 2) / 4; m++) {
                    float4 v = *(const float4*)(row + ixb + 1 + 4 * m);
                    w[1 + 4 * m] = v.x; w[2 + 4 * m] = v.y;
                    w[3 + 4 * m] = v.z; w[4 + 4 * m] = v.w;
                }
                w[WINW - 1] = (ixb + WINW - 1 < WIN) ? row[ixb + WINW - 1] : 0.f;
            }
            if (IN_RELU) {
#pragma unroll
                for (int m = 0; m < WINW; m++) w[m] = fmaxf(w[m], 0.f);
            }
#pragma unroll
            for (int c = 0; c < TCO; c++) {
                const float* wp = wci + c * CIN * KH * KW + ky * KW;
                if constexpr (KW == 4) {
                    float4 wv = *(const float4*)wp;   // 16B aligned: offset mult of 4 floats
                    float wk[4] = {wv.x, wv.y, wv.z, wv.w};
#pragma unroll
                    for (int kx = 0; kx < 4; kx++)
#pragma unroll
                        for (int j = 0; j < TX; j++)
                            acc[c][j] = fmaf(w[j * S + kx], wk[kx], acc[c][j]);
                } else {
#pragma unroll
                    for (int kx = 0; kx < KW; kx++) {
                        float wv = __ldg(wp + kx);
#pragma unroll
                        for (int j = 0; j < TX; j++)
                            acc[c][j] = fmaf(w[j * S + kx], wv, acc[c][j]);
                    }
                }
            }
        }
    }

#pragma unroll
    for (int c = 0; c < TCO; c++) {
        size_t o = (((size_t)b * COUT + (co0 + c)) * HOUT + oy) * WOUT + ox0;
        float v[TX];
#pragma unroll
        for (int j = 0; j < TX; j++) v[j] = acc[c][j];
        if (ADD) {
            float4 r0 = *(const float4*)(res + o);
            float4 r1 = *(const float4*)(res + o + 4);
            v[0] += r0.x; v[1] += r0.y; v[2] += r0.z; v[3] += r0.w;
            v[4] += r1.x; v[5] += r1.y; v[6] += r1.z; v[7] += r1.w;
        }
        if (OUT_RELU) {
#pragma unroll
            for (int j = 0; j < TX; j++) v[j] = fmaxf(v[j], 0.f);
        }
        *(float4*)(out + o)     = make_float4(v[0], v[1], v[2], v[3]);
        *(float4*)(out + o + 4) = make_float4(v[4], v[5], v[6], v[7]);
    }
}

// ---------------------------------------------------------------------------
// ConvTranspose2d(k=4,s=2,p=1) as direct gather, TX=8 + float4 loads.
// ---------------------------------------------------------------------------
template <int TCO, int CIN, int HIN, int WIN, int COUT, int HOUT, int WOUT,
          bool IN_RELU, bool OUT_RELU, bool VEC_ST>
__global__ __launch_bounds__(128)
void deconv_k(const float* __restrict__ in, const float* __restrict__ wt,
              const float* __restrict__ bs, float* __restrict__ out)
{
    constexpr int TX = 8;
    constexpr int TILES = HOUT * WOUT / TX;
    static_assert(TILES % 128 == 0, "tile count must fill blocks");

    int tid = blockIdx.x * 128 + threadIdx.x;
    int ox0 = (tid * TX) % WOUT;     // multiple of 8 -> even
    int oy  = (tid * TX) / WOUT;
    int co0 = blockIdx.y * TCO;
    int b   = blockIdx.z;

    float acc[TCO][TX];
#pragma unroll
    for (int c = 0; c < TCO; c++) {
        float bv = __ldg(bs + co0 + c);
#pragma unroll
        for (int j = 0; j < TX; j++) acc[c][j] = bv;
    }

    const int ixb = ox0 / 2 - 1;
    const int oyp = oy & 1;
    const float* inb = in + (size_t)b * CIN * HIN * WIN;

#pragma unroll 1
    for (int ci = 0; ci < CIN; ci++) {
        const float* ip  = inb + ci * HIN * WIN;
        const float* wci = wt + ((size_t)co0 * CIN + ci) * 16;
#pragma unroll
        for (int t = 0; t < 2; t++) {
            int ky = oyp + 2 * t;
            int iy = (oy - 2 + ky) >> 1;
            if (iy < 0 || iy >= HIN) continue;
            const float* row = ip + iy * WIN;
            float u[6];
            u[0] = (ixb >= 0) ? row[ixb] : 0.f;
            float4 v = *(const float4*)(row + ixb + 1);   // 16B aligned (ox0/2 mult 4)
            u[1] = v.x; u[2] = v.y; u[3] = v.z; u[4] = v.w;
            u[5] = (ixb + 5 < WIN) ? row[ixb + 5] : 0.f;
            if (IN_RELU) {
#pragma unroll
                for (int m = 0; m < 6; m++) u[m] = fmaxf(u[m], 0.f);
            }
#pragma unroll
            for (int c = 0; c < TCO; c++) {
                float4 wv = *(const float4*)(wci + c * CIN * 16 + ky * 4);
#pragma unroll
                for (int j = 0; j < TX; j++) {
                    const int jo = j & 1;
                    const int sh = (j + 1) >> 1;
                    float wl = jo ? wv.y : wv.x;
                    float wh = jo ? wv.w : wv.z;
                    acc[c][j] = fmaf(u[sh],     wl, acc[c][j]);
                    acc[c][j] = fmaf(u[sh + 1], wh, acc[c][j]);
                }
            }
        }
    }

#pragma unroll
    for (int c = 0; c < TCO; c++) {
        size_t o = (((size_t)b * COUT + (co0 + c)) * HOUT + oy) * WOUT + ox0;
        float v[TX];
#pragma unroll
        for (int j = 0; j < TX; j++) {
            v[j] = acc[c][j];
            if (OUT_RELU) v[j] = fmaxf(v[j], 0.f);
        }
        if constexpr (VEC_ST) {
            *(float4*)(out + o)     = make_float4(v[0], v[1], v[2], v[3]);
            *(float4*)(out + o + 4) = make_float4(v[4], v[5], v[6], v[7]);
        } else {
#pragma unroll
            for (int j = 0; j < TX; j++) out[o + j] = v[j];   // out base may be misaligned
        }
    }
}

// ---------------------------------------------------------------------------
// VQ
// ---------------------------------------------------------------------------
__global__ void cnorm_kernel(const float* __restrict__ cb, float* __restrict__ cn)
{
    int k = blockIdx.x * blockDim.x + threadIdx.x;
    if (k >= 512) return;
    const float* c = cb + k * 64;
    float s = 0.f;
#pragma unroll
    for (int d = 0; d < 64; d++) s = fmaf(c[d], c[d], s);
    cn[k] = s;
}

__global__ __launch_bounds__(256)
void vq_kernel(const float* __restrict__ z, const float* __restrict__ cb,
               const float* __restrict__ cn, int* __restrict__ idx,
               float* __restrict__ q, float* __restrict__ err)
{
    int p = blockIdx.x * blockDim.x + threadIdx.x;  // 0..32767
    if (p >= 32768) return;
    int b = p >> 10, s = p & 1023;
    const float* zp = z + (size_t)b * 64 * 1024 + s;
    float zv[64];
#pragma unroll
    for (int d = 0; d < 64; d++) zv[d] = zp[d * 1024];

    float best = 3.4e38f;
    int bk = 0;
#pragma unroll 1
    for (int k = 0; k < 512; k++) {
        const float4* c4 = (const float4*)(cb + (size_t)k * 64);
        float d0 = 0.f, d1 = 0.f, d2 = 0.f, d3 = 0.f;
#pragma unroll
        for (int m = 0; m < 16; m++) {
            float4 cv = __ldg(c4 + m);
            d0 = fmaf(zv[4 * m],     cv.x, d0);
            d1 = fmaf(zv[4 * m + 1], cv.y, d1);
            d2 = fmaf(zv[4 * m + 2], cv.z, d2);
            d3 = fmaf(zv[4 * m + 3], cv.w, d3);
        }
        float dist = __ldg(cn + k) - 2.f * ((d0 + d1) + (d2 + d3));
        if (dist < best) { best = dist; bk = k; }   // strict <: first-min (jnp.argmin)
    }
    idx[p] = bk;
    float* qp = q + (size_t)b * 64 * 1024 + s;
    const float* c = cb + (size_t)bk * 64;
    float e = 0.f;
#pragma unroll
    for (int d = 0; d < 64; d++) {
        float cd = __ldg(c + d);
        qp[d * 1024] = cd;
        float df = zv[d] - cd;
        e = fmaf(df, df, e);
    }
    err[p] = e;
}

__global__ void hist_zero_kernel(int* __restrict__ hist)
{
    int k = blockIdx.x * blockDim.x + threadIdx.x;
    if (k < 512) hist[k] = 0;
}

__global__ void hist_kernel(const int* __restrict__ idx, int* __restrict__ hist)
{
    int p = blockIdx.x * blockDim.x + threadIdx.x;
    if (p < 32768) atomicAdd(&hist[idx[p]], 1);
}

__global__ __launch_bounds__(1024)
void loss_kernel(const float* __restrict__ err, float* __restrict__ out0)
{
    __shared__ float sm[1024];
    float s = 0.f;
    for (int i = threadIdx.x; i < 32768; i += 1024) s += err[i];
    sm[threadIdx.x] = s;
    __syncthreads();
    for (int off = 512; off > 0; off >>= 1) {
        if (threadIdx.x < off) sm[threadIdx.x] += sm[threadIdx.x + off];
        __syncthreads();
    }
    // loss = (1 + beta) * mse, beta = 0.25; mse denominator = 32768 * 64
    if (threadIdx.x == 0) out0[0] = 1.25f * sm[0] / 2097152.0f;
}

__global__ __launch_bounds__(512)
void perp_kernel(const int* __restrict__ hist, float* __restrict__ outp)
{
    __shared__ float sm[512];
    int k = threadIdx.x;
    float p = (float)hist[k] * (1.0f / 32768.0f);
    sm[k] = p * logf(p + 1e-10f);
    __syncthreads();
    for (int off = 256; off > 0; off >>= 1) {
        if (k < off) sm[k] += sm[k + off];
        __syncthreads();
    }
    if (k == 0) outp[0] = expf(-sm[0]);
}

// ---------------------------------------------------------------------------
// Launch
// ---------------------------------------------------------------------------
extern "C" void kernel_launch(void* const* d_in, const int* in_sizes, int n_in,
                              void* d_out, int out_size)
{
    const float* x     = (const float*)d_in[0];
    const float* e_w1  = (const float*)d_in[1];
    const float* e_b1  = (const float*)d_in[2];
    const float* e_w2  = (const float*)d_in[3];
    const float* e_b2  = (const float*)d_in[4];
    const float* e_w3  = (const float*)d_in[5];
    const float* e_b3  = (const float*)d_in[6];
    const float* e_r1a = (const float*)d_in[7];
    const float* e_r1b = (const float*)d_in[8];
    const float* e_r2a = (const float*)d_in[9];
    const float* e_r2b = (const float*)d_in[10];
    const float* pre_w = (const float*)d_in[11];
    const float* pre_b = (const float*)d_in[12];
    const float* cb    = (const float*)d_in[13];
    const float* d_w1  = (const float*)d_in[14];
    const float* d_b1  = (const float*)d_in[15];
    const float* d_r1a = (const float*)d_in[16];
    const float* d_r1b = (const float*)d_in[17];
    const float* d_r2a = (const float*)d_in[18];
    const float* d_r2b = (const float*)d_in[19];
    const float* dt_w1 = (const float*)d_in[20];
    const float* dt_b1 = (const float*)d_in[21];
    const float* dt_w2 = (const float*)d_in[22];
    const float* dt_b2 = (const float*)d_in[23];
    float* out = (float*)d_out;

    float *A, *Bf, *Cc, *T, *Z, *Q, *G, *cn, *err;
    int *idx, *hist;
    cudaGetSymbolAddress((void**)&A,    g_A);
    cudaGetSymbolAddress((void**)&Bf,   g_B);
    cudaGetSymbolAddress((void**)&Cc,   g_C);
    cudaGetSymbolAddress((void**)&T,    g_T);
    cudaGetSymbolAddress((void**)&Z,    g_Z);
    cudaGetSymbolAddress((void**)&Q,    g_Q);
    cudaGetSymbolAddress((void**)&G,    g_G);
    cudaGetSymbolAddress((void**)&cn,   g_cnorm);
    cudaGetSymbolAddress((void**)&err,  g_err);
    cudaGetSymbolAddress((void**)&idx,  g_idx);
    cudaGetSymbolAddress((void**)&hist, g_hist);

    dim3 blk(128);

    // ---- encoder ----
    // e1: [32,3,128,128] -> [32,64,64,64], k4 s2 p1, relu
    conv_k<4,4,2,1,4, 3,128,128, 64,64,64, false,true,true,false>
        <<<dim3(4, 16, 32), blk>>>(x, e_w1, e_b1, A, nullptr);
    // e2: -> [32,128,32,32], k4 s2 p1, relu
    conv_k<4,4,2,1,4, 64,64,64, 128,32,32, false,true,true,false>
        <<<dim3(1, 32, 32), blk>>>(A, e_w2, e_b2, Bf, nullptr);
    // e3: -> [32,128,32,32], k3 s1 p1
    conv_k<3,3,1,1,4, 128,32,32, 128,32,32, false,false,true,false>
        <<<dim3(1, 32, 32), blk>>>(Bf, e_w3, e_b3, Cc, nullptr);
    // encoder res stack (x2), in-place on Cc
    for (int rb = 0; rb < 2; rb++) {
        const float* wa = (rb == 0) ? e_r1a : e_r2a;
        const float* wb = (rb == 0) ? e_r1b : e_r2b;
        conv_k<3,3,1,1,4, 128,32,32, 32,32,32, true,false,false,false>
            <<<dim3(1, 8, 32), blk>>>(Cc, wa, nullptr, T, nullptr);
        conv_k<1,1,1,0,4, 32,32,32, 128,32,32, true,false,false,true>
            <<<dim3(1, 32, 32), blk>>>(T, wb, nullptr, Cc, Cc);
    }
    // pre-VQ 1x1 (fused final-stack ReLU): Cc -> Z [32,64,32,32]
    conv_k<1,1,1,0,4, 128,32,32, 64,32,32, true,false,true,false>
        <<<dim3(1, 16, 32), blk>>>(Cc, pre_w, pre_b, Z, nullptr);

    // ---- vector quantizer ----
    cnorm_kernel<<<2, 256>>>(cb, cn);
    vq_kernel<<<128, 256>>>(Z, cb, cn, idx, Q, err);
    hist_zero_kernel<<<2, 256>>>(hist);
    hist_kernel<<<128, 256>>>(idx, hist);
    loss_kernel<<<1, 1024>>>(err, out);                    // out[0] = loss
    perp_kernel<<<1, 512>>>(hist, out + (out_size - 1));   // last = perplexity

    // ---- decoder ----
    // d1: Q -> G [32,128,32,32], k3 s1 p1
    conv_k<3,3,1,1,4, 64,32,32, 128,32,32, false,false,true,false>
        <<<dim3(1, 32, 32), blk>>>(Q, d_w1, d_b1, G, nullptr);
    // decoder res stack (x2), in-place on G
    for (int rb = 0; rb < 2; rb++) {
        const float* wa = (rb == 0) ? d_r1a : d_r2a;
        const float* wb = (rb == 0) ? d_r1b : d_r2b;
        conv_k<3,3,1,1,4, 128,32,32, 32,32,32, true,false,false,false>
            <<<dim3(1, 8, 32), blk>>>(G, wa, nullptr, T, nullptr);
        conv_k<1,1,1,0,4, 32,32,32, 128,32,32, true,false,false,true>
            <<<dim3(1, 32, 32), blk>>>(T, wb, nullptr, G, G);
    }
    // dt1: G -> A [32,64,64,64], deconv k4 s2 p1, relu-in + relu-out
    deconv_k<4, 128,32,32, 64,64,64, true,true,true>
        <<<dim3(4, 16, 32), blk>>>(G, dt_w1, dt_b1, A);
    // dt2: A -> x_recon [32,3,128,128] into d_out+1 (misaligned base -> scalar stores)
    deconv_k<3, 64,64,64, 3,128,128, false,false,false>
        <<<dim3(16, 1, 32), blk>>>(A, dt_w2, dt_b2, out + 1);
}